// round 2
// baseline (speedup 1.0000x reference)
#include <cuda_runtime.h>
#include <cuda_bf16.h>

// ---------------------------------------------------------------------------
// RGCN layer, decomposed:
//  pre:  rel_w expansion; per-node hs/ht/selfloop*deg; per-edge attention part;
//        counting-sort edges by relation.
//  main: per-relation blocks, rel_w in registers, gather + sigmoid + atomic.
// ---------------------------------------------------------------------------

#define IN_DIM  32
#define RMAX    256
#define NMAX    16384
#define EMAX    204800

__device__ float g_relw[RMAX * IN_DIM * IN_DIM];   // 1 MB
__device__ float g_hs[NMAX * IN_DIM];              // A_src  @ feat, per node
__device__ float g_ht[NMAX * IN_DIM];              // A_tgt  @ feat, per node
__device__ float g_ea[(size_t)EMAX * IN_DIM];      // per-edge attn part (+A_b)
__device__ int   g_perm[EMAX];
__device__ int   g_cnt[RMAX];
__device__ int   g_off[RMAX + 1];
__device__ int   g_cur[RMAX];
__device__ int   g_deg[NMAX];

// ---- zero counters ----------------------------------------------------------
__global__ void k_zero(int N)
{
    int i = blockIdx.x * blockDim.x + threadIdx.x;
    if (i < RMAX) g_cnt[i] = 0;
    if (i < N)    g_deg[i] = 0;
}

// ---- rel_w[r,i,o] = sum_b w_comp[r,b] * weight[b,i,o] ------------------------
__global__ void k_expand_basis(const float* __restrict__ weight,
                               const float* __restrict__ w_comp,
                               int NB)
{
    int r = blockIdx.x;
    const float* wc = w_comp + r * NB;
    for (int io = threadIdx.x; io < IN_DIM * IN_DIM; io += blockDim.x) {
        float acc = 0.f;
        for (int b = 0; b < NB; ++b)
            acc = fmaf(__ldg(wc + b), __ldg(weight + b * (IN_DIM * IN_DIM) + io), acc);
        g_relw[r * (IN_DIM * IN_DIM) + io] = acc;
    }
}

// ---- per-edge: ea = A_b + A_re@re + A_tr@tr ; histograms ---------------------
__global__ void __launch_bounds__(256)
k_edge_pre(const float* __restrict__ ttr,   // total_target_relation [E,32]
           const float* __restrict__ tre,   // total_relation_embed  [E,32]
           const float* __restrict__ A_w,   // [32,128]
           const float* __restrict__ A_b,   // [32]
           const int*   __restrict__ edges, // [2,E]
           const int*   __restrict__ rels,  // [E]
           int E)
{
    const int lane = threadIdx.x & 31;
    const int gw   = (int)((blockIdx.x * blockDim.x + threadIdx.x) >> 5);
    const int nw   = (int)((gridDim.x * blockDim.x) >> 5);

    float are[IN_DIM], atr[IN_DIM];
#pragma unroll
    for (int i = 0; i < IN_DIM; ++i) {
        are[i] = __ldg(A_w + lane * 128 + 2 * IN_DIM + i);  // rel_embed cols
        atr[i] = __ldg(A_w + lane * 128 + 3 * IN_DIM + i);  // target_rel cols
    }
    const float ab = __ldg(A_b + lane);

    for (int e = gw; e < E; e += nw) {
        const float4* rep = (const float4*)(tre + (size_t)e * IN_DIM);
        const float4* trp = (const float4*)(ttr + (size_t)e * IN_DIM);
        float acc0 = ab, acc1 = 0.f;
#pragma unroll
        for (int c = 0; c < IN_DIM / 4; ++c) {
            float4 a = __ldg(rep + c);
            float4 b = __ldg(trp + c);
            acc0 = fmaf(a.x, are[4*c+0], acc0);
            acc1 = fmaf(a.y, are[4*c+1], acc1);
            acc0 = fmaf(a.z, are[4*c+2], acc0);
            acc1 = fmaf(a.w, are[4*c+3], acc1);
            acc0 = fmaf(b.x, atr[4*c+0], acc0);
            acc1 = fmaf(b.y, atr[4*c+1], acc1);
            acc0 = fmaf(b.z, atr[4*c+2], acc0);
            acc1 = fmaf(b.w, atr[4*c+3], acc1);
        }
        g_ea[(size_t)e * IN_DIM + lane] = acc0 + acc1;
        if (lane == 0) {
            atomicAdd(&g_cnt[__ldg(rels + e)], 1);
            atomicAdd(&g_deg[__ldg(edges + E + e)], 1);
        }
    }
}

// ---- prefix sum over relation counts (single block) --------------------------
__global__ void k_scan(int R)
{
    __shared__ int buf[RMAX];
    int tid = threadIdx.x;
    int c = (tid < R) ? g_cnt[tid] : 0;
    buf[tid] = c;
    __syncthreads();
#pragma unroll
    for (int d = 1; d < RMAX; d <<= 1) {
        int v = (tid >= d) ? buf[tid - d] : 0;
        __syncthreads();
        buf[tid] += v;
        __syncthreads();
    }
    if (tid == 0) g_off[0] = 0;
    if (tid < R) {
        g_off[tid + 1] = buf[tid];
        g_cur[tid]     = buf[tid] - c;   // exclusive
    }
}

// ---- scatter edge ids into relation buckets ----------------------------------
__global__ void k_scatter(const int* __restrict__ rels, int E)
{
    int e = blockIdx.x * blockDim.x + threadIdx.x;
    if (e < E) {
        int pos = atomicAdd(&g_cur[__ldg(rels + e)], 1);
        g_perm[pos] = e;
    }
}

// ---- per-node: hs, ht, and out init = deg * (feat @ slw) ----------------------
__global__ void __launch_bounds__(256)
k_node_pre(const float* __restrict__ node_feat,
           const float* __restrict__ A_w,   // [32,128]
           const float* __restrict__ slw,   // [32,32]
           float*       __restrict__ out,
           int N)
{
    const int lane = threadIdx.x & 31;
    const int gw   = (int)((blockIdx.x * blockDim.x + threadIdx.x) >> 5);
    const int nw   = (int)((gridDim.x * blockDim.x) >> 5);

    float aws[IN_DIM], awt[IN_DIM], slc[IN_DIM];
#pragma unroll
    for (int i = 0; i < IN_DIM; ++i) {
        aws[i] = __ldg(A_w + lane * 128 + i);
        awt[i] = __ldg(A_w + lane * 128 + IN_DIM + i);
        slc[i] = __ldg(slw + i * IN_DIM + lane);
    }

    for (int n = gw; n < N; n += nw) {
        const float4* fp = (const float4*)(node_feat + (size_t)n * IN_DIM);
        float hs = 0.f, ht = 0.f, sl = 0.f;
#pragma unroll
        for (int c = 0; c < IN_DIM / 4; ++c) {
            float4 f = __ldg(fp + c);
            hs = fmaf(f.x, aws[4*c+0], hs); ht = fmaf(f.x, awt[4*c+0], ht); sl = fmaf(f.x, slc[4*c+0], sl);
            hs = fmaf(f.y, aws[4*c+1], hs); ht = fmaf(f.y, awt[4*c+1], ht); sl = fmaf(f.y, slc[4*c+1], sl);
            hs = fmaf(f.z, aws[4*c+2], hs); ht = fmaf(f.z, awt[4*c+2], ht); sl = fmaf(f.z, slc[4*c+2], sl);
            hs = fmaf(f.w, aws[4*c+3], hs); ht = fmaf(f.w, awt[4*c+3], ht); sl = fmaf(f.w, slc[4*c+3], sl);
        }
        g_hs[(size_t)n * IN_DIM + lane] = hs;
        g_ht[(size_t)n * IN_DIM + lane] = ht;
        float dg = (float)__ldg(&g_deg[n]);
        out[(size_t)n * IN_DIM + lane] = dg * sl;
    }
}

// ---- main: per-relation buckets, rel_w in registers ---------------------------
__global__ void __launch_bounds__(256)
k_edges_main(const float* __restrict__ node_feat,
             const float* __restrict__ B_w,   // [32]
             const float* __restrict__ B_b,   // [1]
             const int*   __restrict__ edges, // [2,E]
             float*       __restrict__ out,
             int E)
{
    const int r     = blockIdx.x;
    const int start = __ldg(&g_off[r]);
    const int end   = __ldg(&g_off[r + 1]);
    if (start >= end) return;

    const int lane = threadIdx.x & 31;

    float rwc[IN_DIM];   // column `lane` of rel_w[r]
#pragma unroll
    for (int i = 0; i < IN_DIM; ++i)
        rwc[i] = __ldg(&g_relw[r * (IN_DIM * IN_DIM) + i * IN_DIM + lane]);

    const float bw = __ldg(B_w + lane);
    const float bb = __ldg(B_b);

    const int w = blockIdx.y * (blockDim.x >> 5) + (threadIdx.x >> 5);
    const int W = gridDim.y * (blockDim.x >> 5);

    for (int i = start + w; i < end; i += W) {
        const int e = __ldg(&g_perm[i]);
        const int s = __ldg(edges + e);
        const int t = __ldg(edges + E + e);

        float h = __ldg(&g_hs[(size_t)s * IN_DIM + lane])
                + __ldg(&g_ht[(size_t)t * IN_DIM + lane])
                + __ldg(&g_ea[(size_t)e * IN_DIM + lane]);
        h = fmaxf(h, 0.f);

        float p = h * bw;
#pragma unroll
        for (int o = 16; o; o >>= 1)
            p += __shfl_xor_sync(0xffffffffu, p, o);
        const float att = 1.f / (1.f + __expf(-(p + bb)));

        const float4* sp = (const float4*)(node_feat + (size_t)s * IN_DIM);
        float m0 = 0.f, m1 = 0.f;
#pragma unroll
        for (int c = 0; c < IN_DIM / 4; ++c) {
            float4 f = __ldg(sp + c);
            m0 = fmaf(f.x, rwc[4*c+0], m0);
            m1 = fmaf(f.y, rwc[4*c+1], m1);
            m0 = fmaf(f.z, rwc[4*c+2], m0);
            m1 = fmaf(f.w, rwc[4*c+3], m1);
        }
        atomicAdd(out + (size_t)t * IN_DIM + lane, (m0 + m1) * att);
    }
}

extern "C" void kernel_launch(void* const* d_in, const int* in_sizes, int n_in,
                              void* d_out, int out_size)
{
    const float* node_feat = (const float*)d_in[0];
    const float* ttr       = (const float*)d_in[1];
    const float* tre       = (const float*)d_in[2];
    const float* weight    = (const float*)d_in[3];
    const float* w_comp    = (const float*)d_in[4];
    const float* slw       = (const float*)d_in[5];
    const float* A_w       = (const float*)d_in[6];
    const float* A_b       = (const float*)d_in[7];
    const float* B_w       = (const float*)d_in[8];
    const float* B_b       = (const float*)d_in[9];
    const int*   edges     = (const int*)d_in[10];
    const int*   rels      = (const int*)d_in[11];
    float* out = (float*)d_out;

    const int E  = in_sizes[11];
    const int N  = in_sizes[0] / IN_DIM;
    const int NB = in_sizes[3] / (IN_DIM * IN_DIM);
    const int R  = in_sizes[4] / NB;

    int sms = 148;
    cudaDeviceGetAttribute(&sms, cudaDevAttrMultiProcessorCount, 0);

    int mx = (N > RMAX ? N : RMAX);
    k_zero<<<(mx + 255) / 256, 256>>>(N);
    k_expand_basis<<<R, 256>>>(weight, w_comp, NB);
    k_edge_pre<<<2 * sms, 256>>>(ttr, tre, A_w, A_b, edges, rels, E);
    k_scan<<<1, RMAX>>>(R);
    k_scatter<<<(E + 255) / 256, 256>>>(rels, E);
    k_node_pre<<<sms, 256>>>(node_feat, A_w, slw, out, N);
    k_edges_main<<<dim3(R, 4), 256>>>(node_feat, B_w, B_b, edges, out, E);
}